// round 12
// baseline (speedup 1.0000x reference)
#include <cuda_runtime.h>
#include <cstdint>

#define NSAMPLES   524288
#define NFEAT      64
#define NGATES     64
#define NOUT       8
#define BASEN      66            // NFEAT + const0 + const1
#define MAXCONN    130
#define BLK        128
#define STRIDE     129           // odd stride -> conflict-free, no XOR on addr path
#define TRASH      130           // write-only row for padded slots
#define SMEM_BYTES ((MAXCONN + 1) * STRIDE * 4)   // 131 rows = 67596 B -> 3 blocks/SM
#define GRPSZ      8
#define MAXSLOTS   (NGATES * GRPSZ)   // worst case: 64 levels of 1 gate

// Schedule slot: {offA, offB, storeOff, weightByteOff}; weights row 64 = zeros.
struct Params {
    uint4 sched[MAXSLOTS];
    float w[NGATES + 1][NOUT];   // +1 zero row for padded slots
    int   ngroups;
    int   pad[3];
};
__device__   Params g_stage;
__constant__ Params c_p;

// ---------------------------------------------------------------------------
// Prep (64 threads): serial top-2 per gate (softmax monotonic -> top-2 of raw
// masked logits; strict '>' reproduces top_k lower-index tie-break), then
// thread 0 levelizes the DAG in smem and builds a level-aligned 8-gate-group
// schedule; all threads write descriptors/weights to global staging.
// ---------------------------------------------------------------------------
__global__ void __launch_bounds__(64)
prep_kernel(const float* __restrict__ gw,
            const float* __restrict__ ow,
            const float* __restrict__ sc) {
    __shared__ int i1s[NGATES], i2s[NGATES];
    __shared__ int lev[NGATES];
    __shared__ int order[MAXSLOTS];      // slot -> gate index, or -1 (pad)
    __shared__ int nslots_s;
    const int tid = threadIdx.x;

    // --- top-2 of gate_weights[tid, 0 : 66+tid] ---
    {
        const float* row = gw + tid * MAXCONN;
        const int n = BASEN + tid;
        float v1 = -3.4e38f, v2 = -3.4e38f;
        int   i1 = 0, i2 = 0;
        for (int j = 0; j < n; ++j) {
            float v = row[j];
            if (v > v1)      { v2 = v1; i2 = i1; v1 = v; i1 = j; }
            else if (v > v2) { v2 = v;  i2 = j; }
        }
        i1s[tid] = i1; i2s[tid] = i2;
    }
    __syncthreads();

    // --- levelize + schedule (thread 0; tiny, all in smem) ---
    if (tid == 0) {
        int maxlev = 0;
        for (int i = 0; i < NGATES; ++i) {
            int e1 = i1s[i], e2 = i2s[i];
            int l1 = (e1 >= BASEN) ? lev[e1 - BASEN] : 0;   // ops always earlier
            int l2 = (e2 >= BASEN) ? lev[e2 - BASEN] : 0;
            int L = 1 + (l1 > l2 ? l1 : l2);
            lev[i] = L;
            if (L > maxlev) maxlev = L;
        }
        int s = 0;
        for (int L = 1; L <= maxlev; ++L) {
            for (int i = 0; i < NGATES; ++i)
                if (lev[i] == L) order[s++] = i;
            while (s % GRPSZ) order[s++] = -1;     // pad to group boundary
        }
        nslots_s = s;
        g_stage.ngroups = s / GRPSZ;
    }
    __syncthreads();

    // --- write schedule descriptors (parallel over slots) ---
    const int nslots = nslots_s;
    for (int s = tid; s < nslots; s += 64) {
        int gate = order[s];
        uint4 d;
        if (gate >= 0) {
            d.x = (unsigned)(i1s[gate] * STRIDE * 4);
            d.y = (unsigned)(i2s[gate] * STRIDE * 4);
            d.z = (unsigned)((BASEN + gate) * STRIDE * 4);
            d.w = (unsigned)(gate * NOUT * 4);
        } else {                                   // pad: reads const-0 row,
            d.x = (unsigned)(64 * STRIDE * 4);     // writes trash, zero weight
            d.y = (unsigned)(64 * STRIDE * 4);
            d.z = (unsigned)(TRASH * STRIDE * 4);
            d.w = (unsigned)(NGATES * NOUT * 4);
        }
        g_stage.sched[s] = d;
    }
    // --- weights (scale folded); row 64 zeroed ---
#pragma unroll
    for (int j = 0; j < NOUT; ++j) {
        g_stage.w[tid][j] = ow[tid * NOUT + j] * sc[j];
        if (tid == 0) g_stage.w[NGATES][j] = 0.0f;
    }
}

// ---------------------------------------------------------------------------
// Main: one thread = one sample, fp32 smem buffer [entry][sample], STRIDE 129
// (proven conflict-free, no address XOR). Gates execute in level-aligned
// groups of 8: 16 independent LDS dispatched back-to-back, 8 FFMA, 8 STS,
// then the 64 accumulation FFMAs cover the next group's LDS latency.
// No gate in a group depends on another gate in the same group.
// ---------------------------------------------------------------------------
__global__ void __launch_bounds__(BLK, 3)
circuit_kernel(const float* __restrict__ X, float* __restrict__ out) {
    extern __shared__ float sbuf[];
    const int tid = threadIdx.x;
    const long long base = (long long)blockIdx.x * BLK;

    // X transpose (R2-proven): float4 streaming loads, conflict-free STS.
    const float4* Xb = (const float4*)(X + base * NFEAT);
#pragma unroll
    for (int k = 0; k < NFEAT / 4; ++k) {
        float4 v = __ldcs(&Xb[k * BLK + tid]);
        int e = 4 * (k * BLK + tid);
        int s = e >> 6;
        int f = e & 63;
        sbuf[(f + 0) * STRIDE + s] = v.x;
        sbuf[(f + 1) * STRIDE + s] = v.y;
        sbuf[(f + 2) * STRIDE + s] = v.z;
        sbuf[(f + 3) * STRIDE + s] = v.w;
    }
    sbuf[64 * STRIDE + tid] = 0.0f;   // const 0
    sbuf[65 * STRIDE + tid] = 1.0f;   // const 1
    __syncthreads();

    char* col = (char*)(sbuf + tid);  // this sample's column (byte base)
    float acc[NOUT];
#pragma unroll
    for (int j = 0; j < NOUT; ++j) acc[j] = 0.0f;

    const int ng = c_p.ngroups;
    for (int gset = 0; gset < ng; ++gset) {
        const uint4* sd = &c_p.sched[gset * GRPSZ];
        uint4 d[GRPSZ];
        float A[GRPSZ], B[GRPSZ], G[GRPSZ];

        // 16 independent LDS, dispatched back-to-back (intra-group no deps).
#pragma unroll
        for (int u = 0; u < GRPSZ; ++u) {
            d[u] = sd[u];
            A[u] = *(const float*)(col + d[u].x);
            B[u] = *(const float*)(col + d[u].y);
        }
#pragma unroll
        for (int u = 0; u < GRPSZ; ++u)
            G[u] = fmaf(-A[u], B[u], 1.0f);        // g = 1 - a*b
#pragma unroll
        for (int u = 0; u < GRPSZ; ++u)
            *(float*)(col + d[u].z) = G[u];        // 8 STS

        // Accumulation: 64 FFMAs, independent of next group's loads -> they
        // fill the LDS-latency shadow of the following iteration.
#pragma unroll
        for (int u = 0; u < GRPSZ; ++u) {
            const float4* wp = (const float4*)((const char*)c_p.w + d[u].w);
            float4 w0 = wp[0], w1 = wp[1];
            acc[0] = fmaf(G[u], w0.x, acc[0]);
            acc[1] = fmaf(G[u], w0.y, acc[1]);
            acc[2] = fmaf(G[u], w0.z, acc[2]);
            acc[3] = fmaf(G[u], w0.w, acc[3]);
            acc[4] = fmaf(G[u], w1.x, acc[4]);
            acc[5] = fmaf(G[u], w1.y, acc[5]);
            acc[6] = fmaf(G[u], w1.z, acc[6]);
            acc[7] = fmaf(G[u], w1.w, acc[7]);
        }
    }

    float4 r0 = make_float4(acc[0], acc[1], acc[2], acc[3]);
    float4 r1 = make_float4(acc[4], acc[5], acc[6], acc[7]);
    float4* op = (float4*)(out + (base + tid) * NOUT);
    __stcs(&op[0], r0);
    __stcs(&op[1], r1);
}

// ---------------------------------------------------------------------------
// Launch: prep -> ONE memcpy into the constant bank -> main kernel (3 nodes).
// ---------------------------------------------------------------------------
extern "C" void kernel_launch(void* const* d_in, const int* in_sizes, int n_in,
                              void* d_out, int out_size) {
    const float* X  = (const float*)d_in[0];  // (524288, 64)
    const float* gw = (const float*)d_in[1];  // (64, 130)
    const float* ow = (const float*)d_in[2];  // (64, 8)
    const float* sc = (const float*)d_in[3];  // (8,)
    float* out = (float*)d_out;               // (524288, 8)

    cudaFuncSetAttribute((const void*)circuit_kernel,
                         cudaFuncAttributeMaxDynamicSharedMemorySize, SMEM_BYTES);

    prep_kernel<<<1, 64>>>(gw, ow, sc);

    void* gp = nullptr;
    cudaGetSymbolAddress(&gp, g_stage);
    cudaMemcpyToSymbolAsync(c_p, gp, sizeof(Params), 0,
                            cudaMemcpyDeviceToDevice, 0);

    circuit_kernel<<<NSAMPLES / BLK, BLK, SMEM_BYTES>>>(X, out);
}

// round 13
// speedup vs baseline: 1.2555x; 1.2555x over previous
#include <cuda_runtime.h>
#include <cstdint>

#define NSAMPLES   524288
#define NFEAT      64
#define NGATES     64
#define NOUT       8
#define BASEN      66            // NFEAT + const0 + const1
#define MAXCONN    130
#define BLK        128           // threads per block = samples per tile
#define STRIDEF    129           // floats per row (odd -> conflict-free)
#define ROWB       (STRIDEF * 4) // 516 bytes per row
// Row map: 0-63 X(phase0), 64 const0, 65 const1, 66-129 gates, 130-193 X(phase1)
#define XROW1      130
#define NROWS      194
#define SMEM_BYTES (NROWS * ROWB)     // 100104 B -> 2 blocks/SM (8 warps)
#define NT         (NSAMPLES / BLK)   // 4096 tiles
#define GRID       296                // 148 SMs * 2 persistent blocks

struct Params {
    uint2 off[2][NGATES];   // per-phase byte offsets of (a, b) operands
    float w[NGATES][NOUT];  // output_weights * output_scale (pre-folded)
};
__device__   Params g_stage;
__constant__ Params c_p;

// ---------------------------------------------------------------------------
// Prep (64 threads, serial scan — proven-cheap): top-2 of gate_weights[i,
// 0:66+i]. Softmax is monotonic, so top-2 of probs == top-2 of raw masked
// logits; strict '>' reproduces top_k's lower-index-wins tie-breaking.
// Emits per-phase byte offsets (X entries differ by buffer; consts/gates
// shared) and scale-folded weights.
// ---------------------------------------------------------------------------
__global__ void __launch_bounds__(64)
prep_kernel(const float* __restrict__ gw,
            const float* __restrict__ ow,
            const float* __restrict__ sc) {
    const int i = threadIdx.x;            // one thread per gate
    const float* row = gw + i * MAXCONN;
    const int n = BASEN + i;
    float v1 = -3.4e38f, v2 = -3.4e38f;
    int   i1 = 0, i2 = 0;
    for (int j = 0; j < n; ++j) {
        float v = row[j];
        if (v > v1)      { v2 = v1; i2 = i1; v1 = v; i1 = j; }
        else if (v > v2) { v2 = v;  i2 = j; }
    }
    auto enc = [](int e, int ph) -> unsigned {
        int r = (e < NFEAT && ph) ? (XROW1 + e) : e;   // X rows move per phase
        return (unsigned)(r * ROWB);
    };
    g_stage.off[0][i] = make_uint2(enc(i1, 0), enc(i2, 0));
    g_stage.off[1][i] = make_uint2(enc(i1, 1), enc(i2, 1));
#pragma unroll
    for (int j = 0; j < NOUT; ++j)
        g_stage.w[i][j] = ow[i * NOUT + j] * sc[j];
}

// ---------------------------------------------------------------------------
// Main: persistent blocks, double-buffered X rows. Per tile:
//   1. issue 16 LDG.128 for the NEXT tile (held in registers)   <- DRAM busy
//   2. run the proven R2/R4 gate loop on the CURRENT buffer     <- covers lat
//   3. store outputs, transpose-STS the register payload into the back
//      buffer, one __syncthreads, flip phase.
// The gate loop is byte-for-byte the R4 form (prefetch-1 post-STS, zero
// fixups, LDC tables) that measured fastest of all variants.
// ---------------------------------------------------------------------------
__global__ void __launch_bounds__(BLK, 2)
circuit_kernel(const float* __restrict__ X, float* __restrict__ out) {
    extern __shared__ float sbuf[];
    const int tid = threadIdx.x;
    char* sb = (char*)sbuf;

    // Prologue: load first tile into X buffer 0 (R2-proven transpose:
    // e = 4*(k*128+tid) -> sample s=e>>6, feature f=e&63; banks (f+s)%32 CF).
    long long t = blockIdx.x;
    {
        const float4* Xb = (const float4*)(X + t * BLK * NFEAT);
#pragma unroll
        for (int k = 0; k < NFEAT / 4; ++k) {
            float4 v = __ldcs(&Xb[k * BLK + tid]);
            int e = 4 * (k * BLK + tid);
            int s = e >> 6;
            int f = e & 63;
            sbuf[(f + 0) * STRIDEF + s] = v.x;
            sbuf[(f + 1) * STRIDEF + s] = v.y;
            sbuf[(f + 2) * STRIDEF + s] = v.z;
            sbuf[(f + 3) * STRIDEF + s] = v.w;
        }
    }
    sbuf[64 * STRIDEF + tid] = 0.0f;   // const 0 (shared by both phases)
    sbuf[65 * STRIDEF + tid] = 1.0f;   // const 1
    __syncthreads();

    const unsigned m4 = 4u * tid;      // this sample's byte offset in a row
    unsigned ph = 0;

    for (; t < NT; t += GRID) {
        const long long nt = t + GRID;
        const bool hn = nt < NT;

        // --- 1. prefetch next tile into registers (issued before gate loop)
        float4 pv[NFEAT / 4];
        if (hn) {
            const float4* Xn = (const float4*)(X + nt * BLK * NFEAT);
#pragma unroll
            for (int k = 0; k < NFEAT / 4; ++k)
                pv[k] = __ldcs(&Xn[k * BLK + tid]);
        }

        // --- 2. gate loop (exact R4 structure) on current phase's offsets
        const uint2* offp = c_p.off[ph];
        float acc[NOUT];
#pragma unroll
        for (int j = 0; j < NOUT; ++j) acc[j] = 0.0f;

        uint2 o0 = offp[0];
        float a = *(const float*)(sb + o0.x + m4);
        float b = *(const float*)(sb + o0.y + m4);

#pragma unroll
        for (int i = 0; i < NGATES; ++i) {
            float g = fmaf(-a, b, 1.0f);                   // g = 1 - a*b
            *(float*)(sb + (unsigned)((BASEN + i) * ROWB) + m4) = g;

            if (i + 1 < NGATES) {          // post-STS prefetch: never stale
                uint2 o = offp[i + 1];
                a = *(const float*)(sb + o.x + m4);
                b = *(const float*)(sb + o.y + m4);
            }

            float4 w0 = *(const float4*)&c_p.w[i][0];      // 2x LDC.128
            float4 w1 = *(const float4*)&c_p.w[i][4];
            acc[0] = fmaf(g, w0.x, acc[0]);
            acc[1] = fmaf(g, w0.y, acc[1]);
            acc[2] = fmaf(g, w0.z, acc[2]);
            acc[3] = fmaf(g, w0.w, acc[3]);
            acc[4] = fmaf(g, w1.x, acc[4]);
            acc[5] = fmaf(g, w1.y, acc[5]);
            acc[6] = fmaf(g, w1.z, acc[6]);
            acc[7] = fmaf(g, w1.w, acc[7]);
        }

        // --- 3. output + back-buffer fill + barrier
        float4* op = (float4*)(out + (t * BLK + tid) * NOUT);
        __stcs(&op[0], make_float4(acc[0], acc[1], acc[2], acc[3]));
        __stcs(&op[1], make_float4(acc[4], acc[5], acc[6], acc[7]));

        if (hn) {
            float* xb = sbuf + (ph ? 0 : XROW1) * STRIDEF;   // back buffer
#pragma unroll
            for (int k = 0; k < NFEAT / 4; ++k) {
                int e = 4 * (k * BLK + tid);
                int s = e >> 6;
                int f = e & 63;
                xb[(f + 0) * STRIDEF + s] = pv[k].x;
                xb[(f + 1) * STRIDEF + s] = pv[k].y;
                xb[(f + 2) * STRIDEF + s] = pv[k].z;
                xb[(f + 3) * STRIDEF + s] = pv[k].w;
            }
        }
        __syncthreads();
        ph ^= 1;
    }
}

// ---------------------------------------------------------------------------
// Launch: prep -> ONE memcpy into the constant bank -> main kernel (3 nodes).
// ---------------------------------------------------------------------------
extern "C" void kernel_launch(void* const* d_in, const int* in_sizes, int n_in,
                              void* d_out, int out_size) {
    const float* X  = (const float*)d_in[0];  // (524288, 64)
    const float* gw = (const float*)d_in[1];  // (64, 130)
    const float* ow = (const float*)d_in[2];  // (64, 8)
    const float* sc = (const float*)d_in[3];  // (8,)
    float* out = (float*)d_out;               // (524288, 8)

    cudaFuncSetAttribute((const void*)circuit_kernel,
                         cudaFuncAttributeMaxDynamicSharedMemorySize, SMEM_BYTES);

    prep_kernel<<<1, 64>>>(gw, ow, sc);

    void* gp = nullptr;
    cudaGetSymbolAddress(&gp, g_stage);
    cudaMemcpyToSymbolAsync(c_p, gp, sizeof(Params), 0,
                            cudaMemcpyDeviceToDevice, 0);

    circuit_kernel<<<GRID, BLK, SMEM_BYTES>>>(X, out);
}

// round 14
// speedup vs baseline: 1.4797x; 1.1786x over previous
#include <cuda_runtime.h>
#include <cstdint>

#define NSAMPLES   524288
#define NFEAT      64
#define NGATES     64
#define NOUT       8
#define BASEN      66            // NFEAT + const0 + const1
#define MAXCONN    130
#define BLK        128
#define STRIDEF    129           // floats per row (odd -> conflict-free)
#define ROWB       (STRIDEF * 4) // 516 B per row
#define SLOTS      88            // compact rows: 0 trash, 1 c0, 2 c1, 3..live
#define SMEM_FAST  (SLOTS * ROWB)     // 45408 B -> 5 blocks/SM = 20 warps
#define SMEM_FULL  (MAXCONN * ROWB)   // 67080 B (fallback, 3 blocks/SM)
#define NT         (NSAMPLES / BLK)   // 4096 tiles
#define GRID_FULL  296

struct Params {
    uint4    gd[NGATES];     // {offA, offB, offStore, 0} compact byte offsets
    uint2    forig[NGATES];  // full-layout byte offsets (fallback)
    uint4    xoff4[16];      // X row byte offsets, packed 4 features/entry
    unsigned flags;          // 1 = capacity overflow -> fallback runs
    unsigned pad[3];
    float    w[NGATES][NOUT];// output_weights * output_scale (pre-folded)
};
__device__   Params g_stage;
__constant__ Params c_p;

// ---------------------------------------------------------------------------
// Prep (64 threads): serial top-2 per gate (softmax monotonic -> top-2 of raw
// masked logits; strict '>' reproduces top_k lower-index tie-break), one-warp
// ballot/popc slot compaction over all 130 entries, weight folding.
// ---------------------------------------------------------------------------
__global__ void __launch_bounds__(64)
prep_kernel(const float* __restrict__ gw,
            const float* __restrict__ ow,
            const float* __restrict__ sc) {
    __shared__ int si1[NGATES], si2[NGATES];
    __shared__ int slotArr[MAXCONN];
    __shared__ unsigned char needf[MAXCONN];
    const int tid = threadIdx.x;

    needf[tid] = 0; needf[64 + tid] = 0;
    if (tid < 2) needf[128 + tid] = 0;

    {   // top-2 of gate_weights[tid, 0 : 66+tid]
        const float* row = gw + tid * MAXCONN;
        const int n = BASEN + tid;
        float v1 = -3.4e38f, v2 = -3.4e38f;
        int   i1 = 0, i2 = 0;
        for (int j = 0; j < n; ++j) {
            float v = row[j];
            if (v > v1)      { v2 = v1; i2 = i1; v1 = v; i1 = j; }
            else if (v > v2) { v2 = v;  i2 = j; }
        }
        si1[tid] = i1; si2[tid] = i2;
    }
    __syncthreads();
    needf[si1[tid]] = 1; needf[si2[tid]] = 1;
    __syncthreads();

    if (tid < 32) {                      // single-pool prefix compaction
        int running = 3;                 // slots 0/1/2 reserved
        for (int ch = 0; ch < 5; ++ch) {
            int e = ch * 32 + tid;
            bool nd = (e < MAXCONN) && needf[e] && (e != 64) && (e != 65);
            unsigned mask = __ballot_sync(0xffffffffu, nd);
            if (e < MAXCONN) {
                int s;
                if      (e == 64) s = 1;
                else if (e == 65) s = 2;
                else if (nd)      s = running + __popc(mask & ((1u << tid) - 1u));
                else              s = 0;               // dead -> trash row
                slotArr[e] = s;
            }
            running += __popc(mask);
        }
        if (tid == 0) g_stage.flags = (running > SLOTS) ? 1u : 0u;
    }
    __syncthreads();

    {   // descriptors
        int e1 = si1[tid], e2 = si2[tid];
        g_stage.gd[tid] = make_uint4((unsigned)(slotArr[e1] * ROWB),
                                     (unsigned)(slotArr[e2] * ROWB),
                                     (unsigned)(slotArr[BASEN + tid] * ROWB), 0u);
        g_stage.forig[tid] = make_uint2((unsigned)(e1 * ROWB),
                                        (unsigned)(e2 * ROWB));
    }
    if (tid < 16)
        g_stage.xoff4[tid] = make_uint4((unsigned)(slotArr[4 * tid + 0] * ROWB),
                                        (unsigned)(slotArr[4 * tid + 1] * ROWB),
                                        (unsigned)(slotArr[4 * tid + 2] * ROWB),
                                        (unsigned)(slotArr[4 * tid + 3] * ROWB));
#pragma unroll
    for (int j = 0; j < NOUT; ++j)
        g_stage.w[tid][j] = ow[tid * NOUT + j] * sc[j];
}

// ---------------------------------------------------------------------------
// Fast path: EXACT R4 gate loop (post-STS prefetch-1, zero fixups, LDC.128
// tables, always-store with trash row for dead gates), fp32, 1 sample/thread,
// stride-129 rows — but on an 88-row compacted buffer: 5 blocks/SM, 20 warps.
// Transpose trick: feature index f = 4*(tid&15) is k-invariant, so each
// thread loads its 4 row offsets once (one divergent LDC.128).
// ---------------------------------------------------------------------------
__global__ void __launch_bounds__(BLK, 5)
fast_kernel(const float* __restrict__ X, float* __restrict__ out) {
    if (c_p.flags) return;
    extern __shared__ float sbuf[];
    char* sb = (char*)sbuf;
    const int tid = threadIdx.x;
    const long long base = (long long)blockIdx.x * BLK;

    // X transpose into compact rows. Element i = 512k + 4tid:
    //   sample s = 8k + (tid>>4), features f..f+3 with f = 4*(tid&15).
    const uint4 xo = c_p.xoff4[tid & 15];      // per-thread row offsets (once)
    const int h = tid >> 4;
    const float4* Xb = (const float4*)(X + base * NFEAT);
#pragma unroll
    for (int k = 0; k < 16; ++k) {
        float4 v = __ldcs(&Xb[k * BLK + tid]);
        unsigned so = 4u * (unsigned)(8 * k + h);       // sample byte offset
        *(float*)(sb + xo.x + so) = v.x;
        *(float*)(sb + xo.y + so) = v.y;
        *(float*)(sb + xo.z + so) = v.z;
        *(float*)(sb + xo.w + so) = v.w;
    }
    sbuf[1 * STRIDEF + tid] = 0.0f;   // const 0 row
    sbuf[2 * STRIDEF + tid] = 1.0f;   // const 1 row
    __syncthreads();

    char* col = sb + 4u * tid;        // this sample's byte column
    float acc[NOUT];
#pragma unroll
    for (int j = 0; j < NOUT; ++j) acc[j] = 0.0f;

    uint4 d = c_p.gd[0];
    float a = *(const float*)(col + d.x);
    float b = *(const float*)(col + d.y);

#pragma unroll
    for (int i = 0; i < NGATES; ++i) {
        float g = fmaf(-a, b, 1.0f);               // g = 1 - a*b
        *(float*)(col + d.z) = g;                  // STS (trash row if dead)

        if (i + 1 < NGATES) {                      // post-STS prefetch
            uint4 dn = c_p.gd[i + 1];              //  -> never stale
            a = *(const float*)(col + dn.x);
            b = *(const float*)(col + dn.y);
            d = dn;
        }

        float4 w0 = *(const float4*)&c_p.w[i][0];  // 2x LDC.128
        float4 w1 = *(const float4*)&c_p.w[i][4];
        acc[0] = fmaf(g, w0.x, acc[0]);
        acc[1] = fmaf(g, w0.y, acc[1]);
        acc[2] = fmaf(g, w0.z, acc[2]);
        acc[3] = fmaf(g, w0.w, acc[3]);
        acc[4] = fmaf(g, w1.x, acc[4]);
        acc[5] = fmaf(g, w1.y, acc[5]);
        acc[6] = fmaf(g, w1.z, acc[6]);
        acc[7] = fmaf(g, w1.w, acc[7]);
    }

    float4* op = (float4*)(out + (base + tid) * NOUT);
    __stcs(&op[0], make_float4(acc[0], acc[1], acc[2], acc[3]));
    __stcs(&op[1], make_float4(acc[4], acc[5], acc[6], acc[7]));
}

// ---------------------------------------------------------------------------
// Fallback (capacity overflow only): persistent, full 130-row buffer,
// original indices — the proven R2/R4 shape at 3 blocks/SM.
// ---------------------------------------------------------------------------
__global__ void __launch_bounds__(BLK, 3)
full_kernel(const float* __restrict__ X, float* __restrict__ out) {
    if (!c_p.flags) return;
    extern __shared__ float sbuf[];
    char* sb = (char*)sbuf;
    const int tid = threadIdx.x;
    const int f0 = 4 * (tid & 15);
    const int h  = tid >> 4;

    for (long long t = blockIdx.x; t < NT; t += GRID_FULL) {
        const long long base = t * BLK;
        const float4* Xb = (const float4*)(X + base * NFEAT);
#pragma unroll
        for (int k = 0; k < 16; ++k) {
            float4 v = __ldcs(&Xb[k * BLK + tid]);
            int s = 8 * k + h;
            sbuf[(f0 + 0) * STRIDEF + s] = v.x;
            sbuf[(f0 + 1) * STRIDEF + s] = v.y;
            sbuf[(f0 + 2) * STRIDEF + s] = v.z;
            sbuf[(f0 + 3) * STRIDEF + s] = v.w;
        }
        sbuf[64 * STRIDEF + tid] = 0.0f;
        sbuf[65 * STRIDEF + tid] = 1.0f;
        __syncthreads();

        char* col = sb + 4u * tid;
        float acc[NOUT];
#pragma unroll
        for (int j = 0; j < NOUT; ++j) acc[j] = 0.0f;

        uint2 o = c_p.forig[0];
        float a = *(const float*)(col + o.x);
        float b = *(const float*)(col + o.y);
#pragma unroll
        for (int i = 0; i < NGATES; ++i) {
            float g = fmaf(-a, b, 1.0f);
            *(float*)(col + (unsigned)((BASEN + i) * ROWB)) = g;
            if (i + 1 < NGATES) {
                uint2 on = c_p.forig[i + 1];
                a = *(const float*)(col + on.x);
                b = *(const float*)(col + on.y);
            }
            float4 w0 = *(const float4*)&c_p.w[i][0];
            float4 w1 = *(const float4*)&c_p.w[i][4];
            acc[0] = fmaf(g, w0.x, acc[0]);
            acc[1] = fmaf(g, w0.y, acc[1]);
            acc[2] = fmaf(g, w0.z, acc[2]);
            acc[3] = fmaf(g, w0.w, acc[3]);
            acc[4] = fmaf(g, w1.x, acc[4]);
            acc[5] = fmaf(g, w1.y, acc[5]);
            acc[6] = fmaf(g, w1.z, acc[6]);
            acc[7] = fmaf(g, w1.w, acc[7]);
        }
        float4* op = (float4*)(out + (base + tid) * NOUT);
        __stcs(&op[0], make_float4(acc[0], acc[1], acc[2], acc[3]));
        __stcs(&op[1], make_float4(acc[4], acc[5], acc[6], acc[7]));
        __syncthreads();
    }
}

// ---------------------------------------------------------------------------
// Launch: prep -> one memcpy -> fast + cheap guarded fallback (4 nodes).
// ---------------------------------------------------------------------------
extern "C" void kernel_launch(void* const* d_in, const int* in_sizes, int n_in,
                              void* d_out, int out_size) {
    const float* X  = (const float*)d_in[0];  // (524288, 64)
    const float* gw = (const float*)d_in[1];  // (64, 130)
    const float* ow = (const float*)d_in[2];  // (64, 8)
    const float* sc = (const float*)d_in[3];  // (8,)
    float* out = (float*)d_out;               // (524288, 8)

    cudaFuncSetAttribute((const void*)fast_kernel,
                         cudaFuncAttributeMaxDynamicSharedMemorySize, SMEM_FAST);
    cudaFuncSetAttribute((const void*)full_kernel,
                         cudaFuncAttributeMaxDynamicSharedMemorySize, SMEM_FULL);

    prep_kernel<<<1, 64>>>(gw, ow, sc);

    void* gp = nullptr;
    cudaGetSymbolAddress(&gp, g_stage);
    cudaMemcpyToSymbolAsync(c_p, gp, sizeof(Params), 0,
                            cudaMemcpyDeviceToDevice, 0);

    fast_kernel<<<NT, BLK, SMEM_FAST>>>(X, out);
    full_kernel<<<GRID_FULL, BLK, SMEM_FULL>>>(X, out);
}

// round 15
// speedup vs baseline: 1.4876x; 1.0053x over previous
#include <cuda_runtime.h>
#include <cstdint>

#define NSAMPLES   524288
#define NFEAT      64
#define NGATES     64
#define NOUT       8
#define BASEN      66            // NFEAT + const0 + const1
#define MAXCONN    130
#define BLK        128
#define STRIDEF    129           // floats per row (odd -> conflict-free)
#define ROWB       (STRIDEF * 4) // 516 B per row
#define SLOTS      88            // compact rows: 0 trash, 1 c0, 2 c1, 3..live
#define SMEM_FAST  (SLOTS * ROWB)     // 45408 B -> 5 blocks/SM = 20 warps
#define SMEM_FULL  (MAXCONN * ROWB)   // 67080 B (fallback, 3 blocks/SM)
#define NT         (NSAMPLES / BLK)   // 4096 tiles
#define GRID_FULL  296

struct Params {
    uint4    gd[NGATES];     // {offA, offB, offStore, 0} compact byte offsets
    uint2    forig[NGATES];  // full-layout byte offsets (fallback)
    uint4    xoff4[16];      // X row byte offsets, packed 4 features/entry
    unsigned flags;          // 1 = capacity overflow -> fallback runs
    unsigned pad[3];
    float    w[NGATES][NOUT];// output_weights * output_scale (pre-folded)
};
__device__   Params g_stage;
__device__   int    g_si1[NGATES], g_si2[NGATES];
__constant__ Params c_p;

// Lexicographic (value desc, index asc) top-2 insert — reproduces top_k's
// lower-index-wins tie-breaking (softmax is monotonic, so top-2 of probs ==
// top-2 of raw masked logits).
static __device__ __forceinline__ void ins2(float v, int j,
                                            float& v1, int& i1,
                                            float& v2, int& i2) {
    if (v > v1 || (v == v1 && j < i1)) { v2 = v1; i2 = i1; v1 = v; i1 = j; }
    else if (v > v2 || (v == v2 && j < i2)) { v2 = v; i2 = j; }
}

// ---------------------------------------------------------------------------
// prep_top2: one block per gate (64 blocks x 128 threads, 64 SMs parallel).
// Each thread covers <=2 elements; shfl tree merge within warps, tiny smem
// merge across the 4 warps. Writes raw top-2 indices to global staging.
// ---------------------------------------------------------------------------
__global__ void __launch_bounds__(128)
prep_top2(const float* __restrict__ gw) {
    const int g   = blockIdx.x;
    const int tid = threadIdx.x;
    const int n   = BASEN + g;
    const float* row = gw + g * MAXCONN;

    float v1 = -3.4e38f, v2 = -3.4e38f;
    int   i1 = 0x7fffffff, i2 = 0x7fffffff;
    if (tid < n)        ins2(row[tid],       tid,       v1, i1, v2, i2);
    if (tid + 128 < n)  ins2(row[tid + 128], tid + 128, v1, i1, v2, i2);

#pragma unroll
    for (int d = 16; d >= 1; d >>= 1) {
        float ov1 = __shfl_down_sync(0xffffffffu, v1, d);
        int   oi1 = __shfl_down_sync(0xffffffffu, i1, d);
        float ov2 = __shfl_down_sync(0xffffffffu, v2, d);
        int   oi2 = __shfl_down_sync(0xffffffffu, i2, d);
        ins2(ov1, oi1, v1, i1, v2, i2);
        ins2(ov2, oi2, v1, i1, v2, i2);
    }

    __shared__ float sv1[4], sv2[4];
    __shared__ int   sj1[4], sj2[4];
    if ((tid & 31) == 0) {
        int w = tid >> 5;
        sv1[w] = v1; sj1[w] = i1; sv2[w] = v2; sj2[w] = i2;
    }
    __syncthreads();
    if (tid == 0) {
#pragma unroll
        for (int w = 1; w < 4; ++w) {
            ins2(sv1[w], sj1[w], v1, i1, v2, i2);
            ins2(sv2[w], sj2[w], v1, i1, v2, i2);
        }
        g_si1[g] = i1;
        g_si2[g] = i2;
    }
}

// ---------------------------------------------------------------------------
// prep_build (1 block x 64 threads): reads the 64 top-2 pairs (512 B), does
// the proven ballot/popc slot compaction, builds descriptors + folded weights.
// ---------------------------------------------------------------------------
__global__ void __launch_bounds__(64)
prep_build(const float* __restrict__ ow, const float* __restrict__ sc) {
    __shared__ int slotArr[MAXCONN];
    __shared__ unsigned char needf[MAXCONN];
    const int tid = threadIdx.x;

    needf[tid] = 0; needf[64 + tid] = 0;
    if (tid < 2) needf[128 + tid] = 0;
    const int e1 = g_si1[tid], e2 = g_si2[tid];
    __syncthreads();
    needf[e1] = 1; needf[e2] = 1;
    __syncthreads();

    if (tid < 32) {                      // single-pool prefix compaction
        int running = 3;                 // slots 0/1/2 reserved
        for (int ch = 0; ch < 5; ++ch) {
            int e = ch * 32 + tid;
            bool nd = (e < MAXCONN) && needf[e] && (e != 64) && (e != 65);
            unsigned mask = __ballot_sync(0xffffffffu, nd);
            if (e < MAXCONN) {
                int s;
                if      (e == 64) s = 1;
                else if (e == 65) s = 2;
                else if (nd)      s = running + __popc(mask & ((1u << tid) - 1u));
                else              s = 0;               // dead -> trash row
                slotArr[e] = s;
            }
            running += __popc(mask);
        }
        if (tid == 0) g_stage.flags = (running > SLOTS) ? 1u : 0u;
    }
    __syncthreads();

    g_stage.gd[tid] = make_uint4((unsigned)(slotArr[e1] * ROWB),
                                 (unsigned)(slotArr[e2] * ROWB),
                                 (unsigned)(slotArr[BASEN + tid] * ROWB), 0u);
    g_stage.forig[tid] = make_uint2((unsigned)(e1 * ROWB),
                                    (unsigned)(e2 * ROWB));
    if (tid < 16)
        g_stage.xoff4[tid] = make_uint4((unsigned)(slotArr[4 * tid + 0] * ROWB),
                                        (unsigned)(slotArr[4 * tid + 1] * ROWB),
                                        (unsigned)(slotArr[4 * tid + 2] * ROWB),
                                        (unsigned)(slotArr[4 * tid + 3] * ROWB));
#pragma unroll
    for (int j = 0; j < NOUT; ++j)
        g_stage.w[tid][j] = ow[tid * NOUT + j] * sc[j];
}

// ---------------------------------------------------------------------------
// Fast path (UNCHANGED from R14 — measured ~36 us at 20 warps/SM):
// exact R4 gate loop (post-STS prefetch-1, zero fixups, LDC.128 tables,
// always-store with trash row), fp32, 1 sample/thread, stride-129 rows,
// 88-row compacted buffer -> 5 blocks/SM.
// ---------------------------------------------------------------------------
__global__ void __launch_bounds__(BLK, 5)
fast_kernel(const float* __restrict__ X, float* __restrict__ out) {
    if (c_p.flags) return;
    extern __shared__ float sbuf[];
    char* sb = (char*)sbuf;
    const int tid = threadIdx.x;
    const long long base = (long long)blockIdx.x * BLK;

    // X transpose into compact rows. Element i = 512k + 4tid:
    //   sample s = 8k + (tid>>4), features f..f+3 with f = 4*(tid&15).
    const uint4 xo = c_p.xoff4[tid & 15];      // per-thread row offsets (once)
    const int h = tid >> 4;
    const float4* Xb = (const float4*)(X + base * NFEAT);
#pragma unroll
    for (int k = 0; k < 16; ++k) {
        float4 v = __ldcs(&Xb[k * BLK + tid]);
        unsigned so = 4u * (unsigned)(8 * k + h);       // sample byte offset
        *(float*)(sb + xo.x + so) = v.x;
        *(float*)(sb + xo.y + so) = v.y;
        *(float*)(sb + xo.z + so) = v.z;
        *(float*)(sb + xo.w + so) = v.w;
    }
    sbuf[1 * STRIDEF + tid] = 0.0f;   // const 0 row
    sbuf[2 * STRIDEF + tid] = 1.0f;   // const 1 row
    __syncthreads();

    char* col = sb + 4u * tid;        // this sample's byte column
    float acc[NOUT];
#pragma unroll
    for (int j = 0; j < NOUT; ++j) acc[j] = 0.0f;

    uint4 d = c_p.gd[0];
    float a = *(const float*)(col + d.x);
    float b = *(const float*)(col + d.y);

#pragma unroll
    for (int i = 0; i < NGATES; ++i) {
        float g = fmaf(-a, b, 1.0f);               // g = 1 - a*b
        *(float*)(col + d.z) = g;                  // STS (trash row if dead)

        if (i + 1 < NGATES) {                      // post-STS prefetch
            uint4 dn = c_p.gd[i + 1];              //  -> never stale
            a = *(const float*)(col + dn.x);
            b = *(const float*)(col + dn.y);
            d = dn;
        }

        float4 w0 = *(const float4*)&c_p.w[i][0];  // 2x LDC.128
        float4 w1 = *(const float4*)&c_p.w[i][4];
        acc[0] = fmaf(g, w0.x, acc[0]);
        acc[1] = fmaf(g, w0.y, acc[1]);
        acc[2] = fmaf(g, w0.z, acc[2]);
        acc[3] = fmaf(g, w0.w, acc[3]);
        acc[4] = fmaf(g, w1.x, acc[4]);
        acc[5] = fmaf(g, w1.y, acc[5]);
        acc[6] = fmaf(g, w1.z, acc[6]);
        acc[7] = fmaf(g, w1.w, acc[7]);
    }

    float4* op = (float4*)(out + (base + tid) * NOUT);
    __stcs(&op[0], make_float4(acc[0], acc[1], acc[2], acc[3]));
    __stcs(&op[1], make_float4(acc[4], acc[5], acc[6], acc[7]));
}

// ---------------------------------------------------------------------------
// Fallback (capacity overflow only): persistent, full 130-row buffer,
// original indices — proven R2/R4 shape at 3 blocks/SM.
// ---------------------------------------------------------------------------
__global__ void __launch_bounds__(BLK, 3)
full_kernel(const float* __restrict__ X, float* __restrict__ out) {
    if (!c_p.flags) return;
    extern __shared__ float sbuf[];
    char* sb = (char*)sbuf;
    const int tid = threadIdx.x;
    const int f0 = 4 * (tid & 15);
    const int h  = tid >> 4;

    for (long long t = blockIdx.x; t < NT; t += GRID_FULL) {
        const long long base = t * BLK;
        const float4* Xb = (const float4*)(X + base * NFEAT);
#pragma unroll
        for (int k = 0; k < 16; ++k) {
            float4 v = __ldcs(&Xb[k * BLK + tid]);
            int s = 8 * k + h;
            sbuf[(f0 + 0) * STRIDEF + s] = v.x;
            sbuf[(f0 + 1) * STRIDEF + s] = v.y;
            sbuf[(f0 + 2) * STRIDEF + s] = v.z;
            sbuf[(f0 + 3) * STRIDEF + s] = v.w;
        }
        sbuf[64 * STRIDEF + tid] = 0.0f;
        sbuf[65 * STRIDEF + tid] = 1.0f;
        __syncthreads();

        char* col = sb + 4u * tid;
        float acc[NOUT];
#pragma unroll
        for (int j = 0; j < NOUT; ++j) acc[j] = 0.0f;

        uint2 o = c_p.forig[0];
        float a = *(const float*)(col + o.x);
        float b = *(const float*)(col + o.y);
#pragma unroll
        for (int i = 0; i < NGATES; ++i) {
            float g = fmaf(-a, b, 1.0f);
            *(float*)(col + (unsigned)((BASEN + i) * ROWB)) = g;
            if (i + 1 < NGATES) {
                uint2 on = c_p.forig[i + 1];
                a = *(const float*)(col + on.x);
                b = *(const float*)(col + on.y);
            }
            float4 w0 = *(const float4*)&c_p.w[i][0];
            float4 w1 = *(const float4*)&c_p.w[i][4];
            acc[0] = fmaf(g, w0.x, acc[0]);
            acc[1] = fmaf(g, w0.y, acc[1]);
            acc[2] = fmaf(g, w0.z, acc[2]);
            acc[3] = fmaf(g, w0.w, acc[3]);
            acc[4] = fmaf(g, w1.x, acc[4]);
            acc[5] = fmaf(g, w1.y, acc[5]);
            acc[6] = fmaf(g, w1.z, acc[6]);
            acc[7] = fmaf(g, w1.w, acc[7]);
        }
        float4* op = (float4*)(out + (base + tid) * NOUT);
        __stcs(&op[0], make_float4(acc[0], acc[1], acc[2], acc[3]));
        __stcs(&op[1], make_float4(acc[4], acc[5], acc[6], acc[7]));
        __syncthreads();
    }
}

// ---------------------------------------------------------------------------
// Launch: prep_top2 (64 blocks) -> prep_build -> memcpy -> fast + fallback.
// ---------------------------------------------------------------------------
extern "C" void kernel_launch(void* const* d_in, const int* in_sizes, int n_in,
                              void* d_out, int out_size) {
    const float* X  = (const float*)d_in[0];  // (524288, 64)
    const float* gw = (const float*)d_in[1];  // (64, 130)
    const float* ow = (const float*)d_in[2];  // (64, 8)
    const float* sc = (const float*)d_in[3];  // (8,)
    float* out = (float*)d_out;               // (524288, 8)

    cudaFuncSetAttribute((const void*)fast_kernel,
                         cudaFuncAttributeMaxDynamicSharedMemorySize, SMEM_FAST);
    cudaFuncSetAttribute((const void*)full_kernel,
                         cudaFuncAttributeMaxDynamicSharedMemorySize, SMEM_FULL);

    prep_top2<<<NGATES, 128>>>(gw);
    prep_build<<<1, 64>>>(ow, sc);

    void* gp = nullptr;
    cudaGetSymbolAddress(&gp, g_stage);
    cudaMemcpyToSymbolAsync(c_p, gp, sizeof(Params), 0,
                            cudaMemcpyDeviceToDevice, 0);

    fast_kernel<<<NT, BLK, SMEM_FAST>>>(X, out);
    full_kernel<<<GRID_FULL, BLK, SMEM_FULL>>>(X, out);
}